// round 3
// baseline (speedup 1.0000x reference)
#include <cuda_runtime.h>
#include <cuda_bf16.h>
#include <cstdint>

// Problem constants
#define T_TOK 4096      // 2 * 2048 tokens
#define H_DIM 1024      // embed
#define F_DIM 2048      // ffn
#define NE    8         // experts
#define TOT_ROWS (2 * T_TOK)               // exact total routed rows (top-2, distinct experts)
#define OUT_MAIN ((size_t)T_TOK * H_DIM)   // 4,194,304 floats, then logits [T,8]

// ---------------- scratch (device globals: no allocation allowed) ----------
__device__ float g_gbuf[(size_t)T_TOK * H_DIM];        // gate hidden, 16 MB
__device__ float g_hbuf[(size_t)TOT_ROWS * F_DIM];     // compact h, 64 MB
__device__ int   g_cnt[NE];
__device__ int   g_off[NE];                            // exclusive scan of g_cnt
__device__ int   g_idx[NE * T_TOK];                    // per-expert token lists (sparse regions)
__device__ float g_wgt[NE * T_TOK];

// ---------------- kernel 0: zero output + counters -------------------------
__global__ void zero_kernel(float* __restrict__ out_main) {
    size_t i = ((size_t)blockIdx.x * blockDim.x + threadIdx.x) * 4;
    if (i < OUT_MAIN) {
        *(float4*)(out_main + i) = make_float4(0.f, 0.f, 0.f, 0.f);
    }
    if (blockIdx.x == 0 && threadIdx.x < NE) g_cnt[threadIdx.x] = 0;
}

// ---------------- kernel 1: gate GEMM1 + bias + ELU ------------------------
// G[4096][1024] = elu(X[4096][1024] @ W[1024][1024] + b)
// 128x128 tile, K-chunk 8, 2-stage register-prefetch pipeline.
__global__ __launch_bounds__(256) void gate_gemm1(const float* __restrict__ X,
                                                  const float* __restrict__ W,
                                                  const float* __restrict__ b) {
    __shared__ float As[8][128];
    __shared__ float Bs[8][128];
    const int tid = threadIdx.x;
    const int m0 = blockIdx.y * 128;
    const int n0 = blockIdx.x * 128;
    const int tr = tid >> 4, tc = tid & 15;
    const int arow = tid >> 1;
    const int akq  = (tid & 1) * 4;
    const int brow = tid >> 5;
    const int bcol = (tid & 31) * 4;

    const float* aptr = X + (size_t)(m0 + arow) * H_DIM + akq;
    const float* bptr = W + (size_t)brow * 1024 + n0 + bcol;

    float acc[8][8];
#pragma unroll
    for (int i = 0; i < 8; i++)
#pragma unroll
        for (int j = 0; j < 8; j++) acc[i][j] = 0.f;

    // prologue: load first K-slice into registers
    float4 aReg = *(const float4*)aptr; aptr += 8;
    float4 bReg = *(const float4*)bptr; bptr += (size_t)8 * 1024;

    for (int k0 = 0; k0 < H_DIM; k0 += 8) {
        As[akq + 0][arow] = aReg.x; As[akq + 1][arow] = aReg.y;
        As[akq + 2][arow] = aReg.z; As[akq + 3][arow] = aReg.w;
        *(float4*)&Bs[brow][bcol] = bReg;
        __syncthreads();
        if (k0 + 8 < H_DIM) {   // prefetch next slice while computing this one
            aReg = *(const float4*)aptr; aptr += 8;
            bReg = *(const float4*)bptr; bptr += (size_t)8 * 1024;
        }
#pragma unroll
        for (int kk = 0; kk < 8; kk++) {
            float af[8], bf[8];
            *(float4*)&af[0] = *(const float4*)&As[kk][tr * 4];
            *(float4*)&af[4] = *(const float4*)&As[kk][64 + tr * 4];
            *(float4*)&bf[0] = *(const float4*)&Bs[kk][tc * 4];
            *(float4*)&bf[4] = *(const float4*)&Bs[kk][64 + tc * 4];
#pragma unroll
            for (int i = 0; i < 8; i++)
#pragma unroll
                for (int j = 0; j < 8; j++) acc[i][j] += af[i] * bf[j];
        }
        __syncthreads();
    }
#pragma unroll
    for (int i = 0; i < 8; i++) {
        int m = m0 + ((i < 4) ? (tr * 4 + i) : (64 + tr * 4 + i - 4));
        float* grow = g_gbuf + (size_t)m * 1024;
#pragma unroll
        for (int j = 0; j < 8; j++) {
            int c = n0 + ((j < 4) ? (tc * 4 + j) : (64 + tc * 4 + j - 4));
            float v = acc[i][j] + b[c];
            grow[c] = (v > 0.f) ? v : expm1f(v);
        }
    }
}

// ---------------- kernel 2: routing (1 warp / token) -----------------------
__global__ void routing_kernel(const float* __restrict__ gw2,
                               const float* __restrict__ gb2,
                               float* __restrict__ out_logits) {
    int warp = (blockIdx.x * blockDim.x + threadIdx.x) >> 5;
    int lane = threadIdx.x & 31;
    if (warp >= T_TOK) return;
    const float* grow = g_gbuf + (size_t)warp * 1024;
    float acc[NE];
#pragma unroll
    for (int e = 0; e < NE; e++) acc[e] = 0.f;
    for (int k = lane; k < 1024; k += 32) {
        float gv = grow[k];
        const float* w = gw2 + (size_t)k * NE;
#pragma unroll
        for (int e = 0; e < NE; e++) acc[e] += gv * w[e];
    }
#pragma unroll
    for (int e = 0; e < NE; e++)
#pragma unroll
        for (int off = 16; off > 0; off >>= 1)
            acc[e] += __shfl_down_sync(0xffffffffu, acc[e], off);
    if (lane == 0) {
        float logit[NE], mx = -1e30f;
#pragma unroll
        for (int e = 0; e < NE; e++) {
            logit[e] = acc[e] + gb2[e];
            out_logits[(size_t)warp * NE + e] = logit[e];
            mx = fmaxf(mx, logit[e]);
        }
        float p[NE];
#pragma unroll
        for (int e = 0; e < NE; e++) p[e] = expf(logit[e] - mx);
        int e1 = 0;
#pragma unroll
        for (int e = 1; e < NE; e++) if (p[e] > p[e1]) e1 = e;
        int e2 = (e1 == 0) ? 1 : 0;
#pragma unroll
        for (int e = 0; e < NE; e++) if (e != e1 && p[e] > p[e2]) e2 = e;
        float s = p[e1] + p[e2];
        float w1 = p[e1] / s, w2 = p[e2] / s;
        int p1 = atomicAdd(&g_cnt[e1], 1);
        g_idx[e1 * T_TOK + p1] = warp; g_wgt[e1 * T_TOK + p1] = w1;
        int p2 = atomicAdd(&g_cnt[e2], 1);
        g_idx[e2 * T_TOK + p2] = warp; g_wgt[e2 * T_TOK + p2] = w2;
    }
}

// ---------------- kernel 2b: tiny exclusive scan over 8 counters -----------
__global__ void offsets_kernel() {
    if (threadIdx.x == 0) {
        int s = 0;
#pragma unroll
        for (int e = 0; e < NE; e++) { g_off[e] = s; s += g_cnt[e]; }
    }
}

// ---------------- kernel 3: gathered h = relu(x@w1)*(x@w3) -----------------
// Tile 128(M) x 64(N), K-chunk 8, dual-B accumulate, 2-stage pipeline.
__global__ __launch_bounds__(256) void expert_h_kernel(const float* __restrict__ X,
                                                       const float* __restrict__ W1,
                                                       const float* __restrict__ W3) {
    const int e = blockIdx.z;
    const int cnt = g_cnt[e];
    const int r0 = blockIdx.y * 128;
    if (r0 >= cnt) return;
    const int hbase = g_off[e];
    const int n0 = blockIdx.x * 64;

    __shared__ float As[8][128];
    __shared__ float B1s[8][64];
    __shared__ float B2s[8][64];

    const int tid = threadIdx.x;
    const int arow = tid >> 1;
    const int akq  = (tid & 1) * 4;
    const int r = r0 + arow;
    const int tok = (r < cnt) ? g_idx[e * T_TOK + r] : 0;
    const float* aptr = X + (size_t)tok * H_DIM + akq;

    const int half = tid >> 7;          // 0 -> W1, 1 -> W3
    const int tl = tid & 127;
    const int brow = tl >> 4;           // 0..7
    const int bcol = (tl & 15) * 4;     // 0..60
    const float* wbase = half ? W3 : W1;
    const float* bptr = wbase + (size_t)e * H_DIM * F_DIM + (size_t)brow * F_DIM + n0 + bcol;
    float* bs_dst = half ? &B2s[brow][bcol] : &B1s[brow][bcol];

    const int tr = tid >> 4, tc = tid & 15;
    float acc1[8][4], acc2[8][4];
#pragma unroll
    for (int i = 0; i < 8; i++)
#pragma unroll
        for (int j = 0; j < 4; j++) { acc1[i][j] = 0.f; acc2[i][j] = 0.f; }

    float4 aReg = *(const float4*)aptr; aptr += 8;
    float4 bReg = *(const float4*)bptr; bptr += (size_t)8 * F_DIM;

    for (int k0 = 0; k0 < H_DIM; k0 += 8) {
        As[akq + 0][arow] = aReg.x; As[akq + 1][arow] = aReg.y;
        As[akq + 2][arow] = aReg.z; As[akq + 3][arow] = aReg.w;
        *(float4*)bs_dst = bReg;
        __syncthreads();
        if (k0 + 8 < H_DIM) {
            aReg = *(const float4*)aptr; aptr += 8;
            bReg = *(const float4*)bptr; bptr += (size_t)8 * F_DIM;
        }
#pragma unroll
        for (int kk = 0; kk < 8; kk++) {
            float af[8], b1f[4], b2f[4];
            *(float4*)&af[0] = *(const float4*)&As[kk][tr * 4];
            *(float4*)&af[4] = *(const float4*)&As[kk][64 + tr * 4];
            *(float4*)&b1f[0] = *(const float4*)&B1s[kk][tc * 4];
            *(float4*)&b2f[0] = *(const float4*)&B2s[kk][tc * 4];
#pragma unroll
            for (int i = 0; i < 8; i++)
#pragma unroll
                for (int j = 0; j < 4; j++) {
                    acc1[i][j] += af[i] * b1f[j];
                    acc2[i][j] += af[i] * b2f[j];
                }
        }
        __syncthreads();
    }
#pragma unroll
    for (int i = 0; i < 8; i++) {
        int rr = r0 + ((i < 4) ? (tr * 4 + i) : (64 + tr * 4 + i - 4));
        if (rr < cnt) {
            float* hrow = g_hbuf + ((size_t)(hbase + rr)) * F_DIM + n0;
#pragma unroll
            for (int j = 0; j < 4; j++) {
                hrow[tc * 4 + j] = fmaxf(acc1[i][j], 0.f) * acc2[i][j];
            }
        }
    }
}

// ---------------- kernel 4: y = h @ w2, weighted scatter-add ----------------
// 128x128 tile, K-chunk 8, 2-stage pipeline.
__global__ __launch_bounds__(256) void expert_y_kernel(const float* __restrict__ W2,
                                                       float* __restrict__ out) {
    const int e = blockIdx.z;
    const int cnt = g_cnt[e];
    const int r0 = blockIdx.y * 128;
    if (r0 >= cnt) return;
    const int hbase = g_off[e];
    const int n0 = blockIdx.x * 128;

    __shared__ float As[8][128];
    __shared__ float Bs[8][128];

    const int tid = threadIdx.x;
    const int arow = tid >> 1;
    const int akq  = (tid & 1) * 4;
    // clamp rows beyond cnt so loads stay inside the compact buffer
    const int ar = (r0 + arow < cnt) ? (r0 + arow) : (cnt > 0 ? cnt - 1 : 0);
    const float* aptr = g_hbuf + ((size_t)(hbase + ar)) * F_DIM + akq;
    const int brow = tid >> 5;
    const int bcol = (tid & 31) * 4;
    const float* bptr = W2 + (size_t)e * F_DIM * H_DIM + (size_t)brow * H_DIM + n0 + bcol;

    const int tr = tid >> 4, tc = tid & 15;
    float acc[8][8];
#pragma unroll
    for (int i = 0; i < 8; i++)
#pragma unroll
        for (int j = 0; j < 8; j++) acc[i][j] = 0.f;

    float4 aReg = *(const float4*)aptr; aptr += 8;
    float4 bReg = *(const float4*)bptr; bptr += (size_t)8 * H_DIM;

    for (int k0 = 0; k0 < F_DIM; k0 += 8) {
        As[akq + 0][arow] = aReg.x; As[akq + 1][arow] = aReg.y;
        As[akq + 2][arow] = aReg.z; As[akq + 3][arow] = aReg.w;
        *(float4*)&Bs[brow][bcol] = bReg;
        __syncthreads();
        if (k0 + 8 < F_DIM) {
            aReg = *(const float4*)aptr; aptr += 8;
            bReg = *(const float4*)bptr; bptr += (size_t)8 * H_DIM;
        }
#pragma unroll
        for (int kk = 0; kk < 8; kk++) {
            float af[8], bf[8];
            *(float4*)&af[0] = *(const float4*)&As[kk][tr * 4];
            *(float4*)&af[4] = *(const float4*)&As[kk][64 + tr * 4];
            *(float4*)&bf[0] = *(const float4*)&Bs[kk][tc * 4];
            *(float4*)&bf[4] = *(const float4*)&Bs[kk][64 + tc * 4];
#pragma unroll
            for (int i = 0; i < 8; i++)
#pragma unroll
                for (int j = 0; j < 8; j++) acc[i][j] += af[i] * bf[j];
        }
        __syncthreads();
    }
#pragma unroll
    for (int i = 0; i < 8; i++) {
        int rr = r0 + ((i < 4) ? (tr * 4 + i) : (64 + tr * 4 + i - 4));
        if (rr < cnt) {
            int tok = g_idx[e * T_TOK + rr];
            float w = g_wgt[e * T_TOK + rr];
            float* orow = out + (size_t)tok * H_DIM + n0;
#pragma unroll
            for (int j = 0; j < 8; j++) {
                int cc = (j < 4) ? (tc * 4 + j) : (64 + tc * 4 + j - 4);
                atomicAdd(&orow[cc], w * acc[i][j]);
            }
        }
    }
}

// ---------------- launch ----------------------------------------------------
extern "C" void kernel_launch(void* const* d_in, const int* in_sizes, int n_in,
                              void* d_out, int out_size) {
    const float* x   = (const float*)d_in[0];   // [2,2048,1024]
    const float* gw1 = (const float*)d_in[1];   // [1024,1024]
    const float* gb1 = (const float*)d_in[2];   // [1024]
    const float* gw2 = (const float*)d_in[3];   // [1024,8]
    const float* gb2 = (const float*)d_in[4];   // [8]
    const float* w1  = (const float*)d_in[5];   // [8,1024,2048]
    const float* w3  = (const float*)d_in[6];   // [8,1024,2048]
    const float* w2  = (const float*)d_in[7];   // [8,2048,1024]
    float* out_main   = (float*)d_out;
    float* out_logits = (float*)d_out + OUT_MAIN;

    // 0) zero output region + expert counters
    zero_kernel<<<(OUT_MAIN / 4 + 255) / 256, 256>>>(out_main);
    // 1) gate hidden: g = elu(x @ gw1 + gb1)
    gate_gemm1<<<dim3(1024 / 128, T_TOK / 128), 256>>>(x, gw1, gb1);
    // 2) logits, softmax, top-2, build gather lists
    routing_kernel<<<(T_TOK * 32) / 256, 256>>>(gw2, gb2, out_logits);
    // 2b) exclusive scan -> compact h offsets
    offsets_kernel<<<1, 32>>>();
    // 3) h = relu(xg @ w1_e) * (xg @ w3_e) per expert (gathered, compact)
    expert_h_kernel<<<dim3(F_DIM / 64, T_TOK / 128, NE), 256>>>(x, w1, w3);
    // 4) out += combine_w * (h @ w2_e) (scatter)
    expert_y_kernel<<<dim3(H_DIM / 128, T_TOK / 128, NE), 256>>>(w2, out_main);
}

// round 4
// speedup vs baseline: 1.4901x; 1.4901x over previous
#include <cuda_runtime.h>
#include <cuda_bf16.h>
#include <cstdint>

// Problem constants
#define T_TOK 4096      // 2 * 2048 tokens
#define H_DIM 1024      // embed
#define F_DIM 2048      // ffn
#define NE    8         // experts
#define TOT_ROWS (2 * T_TOK)               // exact total routed rows
#define OUT_MAIN ((size_t)T_TOK * H_DIM)   // out floats, then logits [T,8]
#define SP 137                             // padded smem row stride (words)

// ---------------- scratch ---------------------------------------------------
__device__ float g_gbuf[(size_t)T_TOK * H_DIM];        // gate hidden, 16 MB
__device__ float g_hbuf[(size_t)TOT_ROWS * F_DIM];     // compact h, 64 MB
__device__ int   g_cnt[NE];
__device__ int   g_off[NE];
__device__ int   g_idx[NE * T_TOK];
__device__ float g_wgt[NE * T_TOK];

// ---------------- helpers ---------------------------------------------------
__device__ __forceinline__ uint32_t f2tf32(float x) {
    uint32_t r;
    asm("cvt.rna.tf32.f32 %0, %1;" : "=r"(r) : "f"(x));
    return r;
}
__device__ __forceinline__ void mma_tf32(float c[4], uint32_t a0, uint32_t a1,
                                         uint32_t a2, uint32_t a3,
                                         uint32_t b0, uint32_t b1) {
    asm volatile(
        "mma.sync.aligned.m16n8k8.row.col.f32.tf32.tf32.f32 "
        "{%0,%1,%2,%3},{%4,%5,%6,%7},{%8,%9},{%0,%1,%2,%3};"
        : "+f"(c[0]), "+f"(c[1]), "+f"(c[2]), "+f"(c[3])
        : "r"(a0), "r"(a1), "r"(a2), "r"(a3), "r"(b0), "r"(b1));
}

// ---------------- kernel 0: zero output + counters -------------------------
__global__ void zero_kernel(float* __restrict__ out_main) {
    size_t i = ((size_t)blockIdx.x * blockDim.x + threadIdx.x) * 4;
    if (i < OUT_MAIN) *(float4*)(out_main + i) = make_float4(0.f, 0.f, 0.f, 0.f);
    if (blockIdx.x == 0 && threadIdx.x < NE) g_cnt[threadIdx.x] = 0;
}

// ---------------- kernel 1: gate GEMM1 + bias + ELU (fp32, unchanged) ------
__global__ __launch_bounds__(256) void gate_gemm1(const float* __restrict__ X,
                                                  const float* __restrict__ W,
                                                  const float* __restrict__ b) {
    __shared__ float As[8][128];
    __shared__ float Bs[8][128];
    const int tid = threadIdx.x;
    const int m0 = blockIdx.y * 128;
    const int n0 = blockIdx.x * 128;
    const int tr = tid >> 4, tc = tid & 15;
    const int arow = tid >> 1;
    const int akq  = (tid & 1) * 4;
    const int brow = tid >> 5;
    const int bcol = (tid & 31) * 4;

    const float* aptr = X + (size_t)(m0 + arow) * H_DIM + akq;
    const float* bptr = W + (size_t)brow * 1024 + n0 + bcol;

    float acc[8][8];
#pragma unroll
    for (int i = 0; i < 8; i++)
#pragma unroll
        for (int j = 0; j < 8; j++) acc[i][j] = 0.f;

    float4 aReg = *(const float4*)aptr; aptr += 8;
    float4 bReg = *(const float4*)bptr; bptr += (size_t)8 * 1024;

    for (int k0 = 0; k0 < H_DIM; k0 += 8) {
        As[akq + 0][arow] = aReg.x; As[akq + 1][arow] = aReg.y;
        As[akq + 2][arow] = aReg.z; As[akq + 3][arow] = aReg.w;
        *(float4*)&Bs[brow][bcol] = bReg;
        __syncthreads();
        if (k0 + 8 < H_DIM) {
            aReg = *(const float4*)aptr; aptr += 8;
            bReg = *(const float4*)bptr; bptr += (size_t)8 * 1024;
        }
#pragma unroll
        for (int kk = 0; kk < 8; kk++) {
            float af[8], bf[8];
            *(float4*)&af[0] = *(const float4*)&As[kk][tr * 4];
            *(float4*)&af[4] = *(const float4*)&As[kk][64 + tr * 4];
            *(float4*)&bf[0] = *(const float4*)&Bs[kk][tc * 4];
            *(float4*)&bf[4] = *(const float4*)&Bs[kk][64 + tc * 4];
#pragma unroll
            for (int i = 0; i < 8; i++)
#pragma unroll
                for (int j = 0; j < 8; j++) acc[i][j] += af[i] * bf[j];
        }
        __syncthreads();
    }
#pragma unroll
    for (int i = 0; i < 8; i++) {
        int m = m0 + ((i < 4) ? (tr * 4 + i) : (64 + tr * 4 + i - 4));
        float* grow = g_gbuf + (size_t)m * 1024;
#pragma unroll
        for (int j = 0; j < 8; j++) {
            int c = n0 + ((j < 4) ? (tc * 4 + j) : (64 + tc * 4 + j - 4));
            float v = acc[i][j] + b[c];
            grow[c] = (v > 0.f) ? v : expm1f(v);
        }
    }
}

// ---------------- kernel 2: routing (fp32, unchanged) ----------------------
__global__ void routing_kernel(const float* __restrict__ gw2,
                               const float* __restrict__ gb2,
                               float* __restrict__ out_logits) {
    int warp = (blockIdx.x * blockDim.x + threadIdx.x) >> 5;
    int lane = threadIdx.x & 31;
    if (warp >= T_TOK) return;
    const float* grow = g_gbuf + (size_t)warp * 1024;
    float acc[NE];
#pragma unroll
    for (int e = 0; e < NE; e++) acc[e] = 0.f;
    for (int k = lane; k < 1024; k += 32) {
        float gv = grow[k];
        const float* w = gw2 + (size_t)k * NE;
#pragma unroll
        for (int e = 0; e < NE; e++) acc[e] += gv * w[e];
    }
#pragma unroll
    for (int e = 0; e < NE; e++)
#pragma unroll
        for (int off = 16; off > 0; off >>= 1)
            acc[e] += __shfl_down_sync(0xffffffffu, acc[e], off);
    if (lane == 0) {
        float logit[NE], mx = -1e30f;
#pragma unroll
        for (int e = 0; e < NE; e++) {
            logit[e] = acc[e] + gb2[e];
            out_logits[(size_t)warp * NE + e] = logit[e];
            mx = fmaxf(mx, logit[e]);
        }
        float p[NE];
#pragma unroll
        for (int e = 0; e < NE; e++) p[e] = expf(logit[e] - mx);
        int e1 = 0;
#pragma unroll
        for (int e = 1; e < NE; e++) if (p[e] > p[e1]) e1 = e;
        int e2 = (e1 == 0) ? 1 : 0;
#pragma unroll
        for (int e = 0; e < NE; e++) if (e != e1 && p[e] > p[e2]) e2 = e;
        float s = p[e1] + p[e2];
        float w1 = p[e1] / s, w2 = p[e2] / s;
        int p1 = atomicAdd(&g_cnt[e1], 1);
        g_idx[e1 * T_TOK + p1] = warp; g_wgt[e1 * T_TOK + p1] = w1;
        int p2 = atomicAdd(&g_cnt[e2], 1);
        g_idx[e2 * T_TOK + p2] = warp; g_wgt[e2 * T_TOK + p2] = w2;
    }
}

// ---------------- kernel 2b: offsets ----------------------------------------
__global__ void offsets_kernel() {
    if (threadIdx.x == 0) {
        int s = 0;
#pragma unroll
        for (int e = 0; e < NE; e++) { g_off[e] = s; s += g_cnt[e]; }
    }
}

// ---------------- kernel 3: h = relu(x@w1)*(x@w3), tf32 MMA ----------------
// Block: 128 rows x 64 real ffn cols. B tile interleaves W1/W3 at 8-col
// granularity: Bs cols [16s..16s+7] = W1[8s..8s+7], [16s+8..16s+15] = W3 same.
// 8 warps in 4x2; each warp 32M x 64 Bs-cols (= 32 real cols, both streams).
__global__ __launch_bounds__(256) void expert_h_mma(const float* __restrict__ X,
                                                    const float* __restrict__ W1,
                                                    const float* __restrict__ W3) {
    const int e = blockIdx.z;
    const int cnt = g_cnt[e];
    const int r0 = blockIdx.y * 128;
    if (r0 >= cnt) return;
    const int hbase = g_off[e];
    const int n0r = blockIdx.x * 64;     // real ffn column offset

    __shared__ uint32_t As[32][SP];
    __shared__ uint32_t Bs[32][SP];

    const int tid = threadIdx.x;
    // A staging: transpose [m][k] -> As[k][m]; 16 k-contig floats/thread
    const int am  = tid >> 1;
    const int akb = (tid & 1) * 16;
    const int arr = (r0 + am < cnt) ? (r0 + am) : (cnt - 1);
    const int tok = g_idx[e * T_TOK + arr];
    const float* aPtr = X + (size_t)tok * H_DIM + akb;
    // B staging: k = tid>>3 (0..31), sel = tid&7 -> 8 W1 cols + 8 W3 cols
    const int bk  = tid >> 3;
    const int sel = tid & 7;
    const float* b1Ptr = W1 + (size_t)e * H_DIM * F_DIM + (size_t)bk * F_DIM + n0r + 8 * sel;
    const float* b3Ptr = W3 + (size_t)e * H_DIM * F_DIM + (size_t)bk * F_DIM + n0r + 8 * sel;

    const int w = tid >> 5, lane = tid & 31;
    const int gq = lane >> 2, t4 = lane & 3;
    const int mw = (w >> 1) * 32;
    const int nw = (w & 1) * 64;

    float acc[2][8][4];
#pragma unroll
    for (int t = 0; t < 2; t++)
#pragma unroll
        for (int j = 0; j < 8; j++)
#pragma unroll
            for (int r = 0; r < 4; r++) acc[t][j][r] = 0.f;

    float4 pa[4], p1[2], p3[2];
#pragma unroll
    for (int q = 0; q < 4; q++) pa[q] = *(const float4*)(aPtr + q * 4);
#pragma unroll
    for (int q = 0; q < 2; q++) { p1[q] = *(const float4*)(b1Ptr + q * 4);
                                  p3[q] = *(const float4*)(b3Ptr + q * 4); }

    for (int k0 = 0; k0 < H_DIM; k0 += 32) {
#pragma unroll
        for (int q = 0; q < 4; q++) {
            As[akb + q * 4 + 0][am] = f2tf32(pa[q].x);
            As[akb + q * 4 + 1][am] = f2tf32(pa[q].y);
            As[akb + q * 4 + 2][am] = f2tf32(pa[q].z);
            As[akb + q * 4 + 3][am] = f2tf32(pa[q].w);
        }
#pragma unroll
        for (int q = 0; q < 2; q++) {
            Bs[bk][16 * sel + q * 4 + 0] = f2tf32(p1[q].x);
            Bs[bk][16 * sel + q * 4 + 1] = f2tf32(p1[q].y);
            Bs[bk][16 * sel + q * 4 + 2] = f2tf32(p1[q].z);
            Bs[bk][16 * sel + q * 4 + 3] = f2tf32(p1[q].w);
            Bs[bk][16 * sel + 8 + q * 4 + 0] = f2tf32(p3[q].x);
            Bs[bk][16 * sel + 8 + q * 4 + 1] = f2tf32(p3[q].y);
            Bs[bk][16 * sel + 8 + q * 4 + 2] = f2tf32(p3[q].z);
            Bs[bk][16 * sel + 8 + q * 4 + 3] = f2tf32(p3[q].w);
        }
        __syncthreads();
        if (k0 + 32 < H_DIM) {
            aPtr += 32; b1Ptr += (size_t)32 * F_DIM; b3Ptr += (size_t)32 * F_DIM;
#pragma unroll
            for (int q = 0; q < 4; q++) pa[q] = *(const float4*)(aPtr + q * 4);
#pragma unroll
            for (int q = 0; q < 2; q++) { p1[q] = *(const float4*)(b1Ptr + q * 4);
                                          p3[q] = *(const float4*)(b3Ptr + q * 4); }
        }
#pragma unroll
        for (int ks = 0; ks < 4; ks++) {
            const int kk = ks * 8;
            uint32_t a[2][4];
#pragma unroll
            for (int t = 0; t < 2; t++) {
                a[t][0] = As[kk + t4][mw + t * 16 + gq];
                a[t][1] = As[kk + t4][mw + t * 16 + gq + 8];
                a[t][2] = As[kk + t4 + 4][mw + t * 16 + gq];
                a[t][3] = As[kk + t4 + 4][mw + t * 16 + gq + 8];
            }
            uint32_t b[8][2];
#pragma unroll
            for (int j = 0; j < 8; j++) {
                b[j][0] = Bs[kk + t4][nw + j * 8 + gq];
                b[j][1] = Bs[kk + t4 + 4][nw + j * 8 + gq];
            }
#pragma unroll
            for (int t = 0; t < 2; t++)
#pragma unroll
                for (int j = 0; j < 8; j++)
                    mma_tf32(acc[t][j], a[t][0], a[t][1], a[t][2], a[t][3],
                             b[j][0], b[j][1]);
        }
        __syncthreads();
    }
    // epilogue: pair even/odd n8 tiles -> h = relu(c1) * c3
#pragma unroll
    for (int t = 0; t < 2; t++)
#pragma unroll
        for (int half = 0; half < 2; half++) {
            int rr = r0 + mw + 16 * t + 8 * half + gq;
            if (rr < cnt) {
                float* hrow = g_hbuf + (size_t)(hbase + rr) * F_DIM + n0r;
#pragma unroll
                for (int u = 0; u < 4; u++) {
                    int ncol = (nw >> 1) + 8 * u + t4 * 2;
                    float v1a = acc[t][2 * u][2 * half + 0];
                    float v3a = acc[t][2 * u + 1][2 * half + 0];
                    float v1b = acc[t][2 * u][2 * half + 1];
                    float v3b = acc[t][2 * u + 1][2 * half + 1];
                    float2 hv = make_float2(fmaxf(v1a, 0.f) * v3a,
                                            fmaxf(v1b, 0.f) * v3b);
                    *(float2*)(hrow + ncol) = hv;
                }
            }
        }
}

// ---------------- kernel 4: y = h @ w2, tf32 MMA, weighted scatter ----------
// Block 128 rows x 128 out cols; 8 warps 4x2 (32M x 64N each).
__global__ __launch_bounds__(256) void expert_y_mma(const float* __restrict__ W2,
                                                    float* __restrict__ out) {
    const int e = blockIdx.z;
    const int cnt = g_cnt[e];
    const int r0 = blockIdx.y * 128;
    if (r0 >= cnt) return;
    const int hbase = g_off[e];
    const int n0 = blockIdx.x * 128;

    __shared__ uint32_t As[32][SP];
    __shared__ uint32_t Bs[32][SP];

    const int tid = threadIdx.x;
    const int am  = tid >> 1;
    const int akb = (tid & 1) * 16;
    const int arr = (r0 + am < cnt) ? (r0 + am) : (cnt - 1);
    const float* aPtr = g_hbuf + (size_t)(hbase + arr) * F_DIM + akb;
    const int bk = tid >> 3;
    const int bn = (tid & 7) * 16;
    const float* bPtr = W2 + (size_t)e * F_DIM * H_DIM + (size_t)bk * H_DIM + n0 + bn;

    const int w = tid >> 5, lane = tid & 31;
    const int gq = lane >> 2, t4 = lane & 3;
    const int mw = (w >> 1) * 32;
    const int nw = (w & 1) * 64;

    float acc[2][8][4];
#pragma unroll
    for (int t = 0; t < 2; t++)
#pragma unroll
        for (int j = 0; j < 8; j++)
#pragma unroll
            for (int r = 0; r < 4; r++) acc[t][j][r] = 0.f;

    float4 pa[4], pb[4];
#pragma unroll
    for (int q = 0; q < 4; q++) { pa[q] = *(const float4*)(aPtr + q * 4);
                                  pb[q] = *(const float4*)(bPtr + q * 4); }

    for (int k0 = 0; k0 < F_DIM; k0 += 32) {
#pragma unroll
        for (int q = 0; q < 4; q++) {
            As[akb + q * 4 + 0][am] = f2tf32(pa[q].x);
            As[akb + q * 4 + 1][am] = f2tf32(pa[q].y);
            As[akb + q * 4 + 2][am] = f2tf32(pa[q].z);
            As[akb + q * 4 + 3][am] = f2tf32(pa[q].w);
            Bs[bk][bn + q * 4 + 0] = f2tf32(pb[q].x);
            Bs[bk][bn + q * 4 + 1] = f2tf32(pb[q].y);
            Bs[bk][bn + q * 4 + 2] = f2tf32(pb[q].z);
            Bs[bk][bn + q * 4 + 3] = f2tf32(pb[q].w);
        }
        __syncthreads();
        if (k0 + 32 < F_DIM) {
            aPtr += 32; bPtr += (size_t)32 * H_DIM;
#pragma unroll
            for (int q = 0; q < 4; q++) { pa[q] = *(const float4*)(aPtr + q * 4);
                                          pb[q] = *(const float4*)(bPtr + q * 4); }
        }
#pragma unroll
        for (int ks = 0; ks < 4; ks++) {
            const int kk = ks * 8;
            uint32_t a[2][4];
#pragma unroll
            for (int t = 0; t < 2; t++) {
                a[t][0] = As[kk + t4][mw + t * 16 + gq];
                a[t][1] = As[kk + t4][mw + t * 16 + gq + 8];
                a[t][2] = As[kk + t4 + 4][mw + t * 16 + gq];
                a[t][3] = As[kk + t4 + 4][mw + t * 16 + gq + 8];
            }
            uint32_t b[8][2];
#pragma unroll
            for (int j = 0; j < 8; j++) {
                b[j][0] = Bs[kk + t4][nw + j * 8 + gq];
                b[j][1] = Bs[kk + t4 + 4][nw + j * 8 + gq];
            }
#pragma unroll
            for (int t = 0; t < 2; t++)
#pragma unroll
                for (int j = 0; j < 8; j++)
                    mma_tf32(acc[t][j], a[t][0], a[t][1], a[t][2], a[t][3],
                             b[j][0], b[j][1]);
        }
        __syncthreads();
    }
    // epilogue: weighted atomic scatter
#pragma unroll
    for (int t = 0; t < 2; t++)
#pragma unroll
        for (int half = 0; half < 2; half++) {
            int rr = r0 + mw + 16 * t + 8 * half + gq;
            if (rr < cnt) {
                int tok = g_idx[e * T_TOK + rr];
                float wv = g_wgt[e * T_TOK + rr];
                float* orow = out + (size_t)tok * H_DIM + n0 + nw;
#pragma unroll
                for (int j = 0; j < 8; j++) {
                    int c = j * 8 + t4 * 2;
                    atomicAdd(&orow[c + 0], wv * acc[t][j][2 * half + 0]);
                    atomicAdd(&orow[c + 1], wv * acc[t][j][2 * half + 1]);
                }
            }
        }
}

// ---------------- launch ----------------------------------------------------
extern "C" void kernel_launch(void* const* d_in, const int* in_sizes, int n_in,
                              void* d_out, int out_size) {
    const float* x   = (const float*)d_in[0];
    const float* gw1 = (const float*)d_in[1];
    const float* gb1 = (const float*)d_in[2];
    const float* gw2 = (const float*)d_in[3];
    const float* gb2 = (const float*)d_in[4];
    const float* w1  = (const float*)d_in[5];
    const float* w3  = (const float*)d_in[6];
    const float* w2  = (const float*)d_in[7];
    float* out_main   = (float*)d_out;
    float* out_logits = (float*)d_out + OUT_MAIN;

    zero_kernel<<<(OUT_MAIN / 4 + 255) / 256, 256>>>(out_main);
    gate_gemm1<<<dim3(1024 / 128, T_TOK / 128), 256>>>(x, gw1, gb1);
    routing_kernel<<<(T_TOK * 32) / 256, 256>>>(gw2, gb2, out_logits);
    offsets_kernel<<<1, 32>>>();
    expert_h_mma<<<dim3(F_DIM / 64, T_TOK / 128, NE), 256>>>(x, w1, w3);
    expert_y_mma<<<dim3(H_DIM / 128, T_TOK / 128, NE), 256>>>(w2, out_main);
}